// round 4
// baseline (speedup 1.0000x reference)
#include <cuda_runtime.h>
#include <stdint.h>

#define NN 100000
#define EE 3200000
#define TT 8
#define FF 64

#define DPB 32                 // dsts per block in fused kernel
#define XSS 520                // smem row stride (floats): 520%32=8 -> conflict-free
#define FUSED_SMEM (DPB * XSS * 4)

// ---------------- device scratch (allocation-free) ----------------
__device__ float g_h1[(size_t)NN * FF];       // 25.6 MB
__device__ int   g_pack[EE];                  // src | (t<<17)
__device__ int   g_edst[EE];                  // dst
__device__ int   g_sedge[EE];                 // packed, sorted by dst
__device__ int   g_cnt[NN];
__device__ int   g_off[NN + 1];
__device__ int   g_cur[NN];
__device__ int   g_mode;                      // 1 = int64 indices, 0 = int32

// f32x2 packed-FMA helpers
#define FMA2(acc, a, b) asm("fma.rn.f32x2 %0, %1, %2, %0;" : "+l"(acc) : "l"(a), "l"(b))
__device__ __forceinline__ unsigned long long pack2(float lo, float hi) {
    unsigned long long r;
    asm("mov.b64 %0, {%1, %2};" : "=l"(r) : "r"(__float_as_uint(lo)), "r"(__float_as_uint(hi)));
    return r;
}
__device__ __forceinline__ float2 unpack2(unsigned long long v) {
    unsigned int lo, hi;
    asm("mov.b64 {%0, %1}, %2;" : "=r"(lo), "=r"(hi) : "l"(v));
    return make_float2(__uint_as_float(lo), __uint_as_float(hi));
}

// ---------------- dtype detection ----------------
__global__ void k_detect(const int* __restrict__ ei) {
    __shared__ int any_nonzero;
    if (threadIdx.x == 0) any_nonzero = 0;
    __syncthreads();
    int v = ei[2 * threadIdx.x + 1];
    if (v != 0) atomicExch(&any_nonzero, 1);
    __syncthreads();
    if (threadIdx.x == 0) g_mode = (any_nonzero == 0) ? 1 : 0;
}

__global__ void k_zero_cnt(void) {
    int i = blockIdx.x * 256 + threadIdx.x;
    if (i < NN) g_cnt[i] = 0;
}

// ---------------- edge prep + histogram (one pass) ----------------
__global__ void k_prep_hist(const void* __restrict__ ei_raw,
                            const void* __restrict__ ti_raw) {
    int e = blockIdx.x * blockDim.x + threadIdx.x;
    if (e >= EE) return;
    int src, dst, t;
    if (g_mode) {
        const long long* ei = (const long long*)ei_raw;
        const long long* ti = (const long long*)ti_raw;
        src = (int)ei[e];
        dst = (int)ei[(size_t)EE + e];
        t   = (int)ti[e];
    } else {
        const int* ei = (const int*)ei_raw;
        const int* ti = (const int*)ti_raw;
        src = ei[e];
        dst = ei[EE + e];
        t   = ti[e];
    }
    g_pack[e] = src | (t << 17);
    g_edst[e] = dst;
    atomicAdd(&g_cnt[dst], 1);
}

// ---------------- single-block exclusive scan ----------------
__global__ void __launch_bounds__(1024) k_scan(void) {
    __shared__ int ps[1024];
    const int CH = 98;
    int tid = threadIdx.x;
    int base = tid * CH;
    int s = 0;
    for (int i = 0; i < CH; i++) {
        int idx = base + i;
        if (idx < NN) s += __ldg(&g_cnt[idx]);
    }
    ps[tid] = s;
    __syncthreads();
    for (int off = 1; off < 1024; off <<= 1) {
        int v = 0;
        if (tid >= off) v = ps[tid - off];
        __syncthreads();
        if (tid >= off) ps[tid] += v;
        __syncthreads();
    }
    int run = (tid == 0) ? 0 : ps[tid - 1];
    for (int i = 0; i < CH; i++) {
        int idx = base + i;
        if (idx < NN) {
            g_off[idx] = run;
            g_cur[idx] = run;
            run += __ldg(&g_cnt[idx]);
        }
    }
    if (tid == 1023) g_off[NN] = EE;
}

// ---------------- permute edges into dst-sorted order ----------------
__global__ void k_permute(void) {
    int e = blockIdx.x * 256 + threadIdx.x;
    if (e >= EE) return;
    int d = g_edst[e];
    int pos = atomicAdd(&g_cur[d], 1);
    g_sedge[pos] = g_pack[e];
}

// ---------------- fused: aggregate (smem) + GEMM + bias + relu -------------
// block = 256 threads, DPB=32 dsts. Phase A: half-warp per dst segment.
// Phase B: [32,512] @ [512,64] FFMA2, W via __ldg (L1-resident).
__global__ void __launch_bounds__(256) k_fused(const float* __restrict__ xin,
                                               const float* __restrict__ W,
                                               const float* __restrict__ bias,
                                               float* __restrict__ out) {
    extern __shared__ float xs[];             // [DPB][XSS]
    int tid = threadIdx.x;
    int warpid = tid >> 5, lane = tid & 31;
    int nb = blockIdx.x * DPB;

    // zero the 32x512 accumulator region
    float4 z4 = make_float4(0.f, 0.f, 0.f, 0.f);
#pragma unroll
    for (int i = tid; i < DPB * 128; i += 256) {
        int row = i >> 7, col = i & 127;
        *(float4*)&xs[row * XSS + col * 4] = z4;
    }
    __syncthreads();

    // Phase A: aggregate. warp handles 4 dsts as 2 sequential half-warp pairs.
    {
        int eh = lane >> 4;                   // half-warp id
        int li = lane & 15;                   // float4 lane within half
        const float4* x4 = (const float4*)xin;
#pragma unroll
        for (int p = 0; p < 2; p++) {
            int slot = warpid * 4 + p * 2 + eh;
            int d = nb + slot;
            int s  = __ldg(&g_off[d]);
            int en = __ldg(&g_off[d + 1]);
            float4* srow = (float4*)&xs[slot * XSS];
            for (int e = s; e < en; e++) {
                int v = __ldg(&g_sedge[e]);
                float4 xv = __ldg(&x4[(size_t)(v & 0x1FFFF) * 16 + li]);
                int t = v >> 17;
                float4 c = srow[t * 16 + li];
                c.x += xv.x; c.y += xv.y; c.z += xv.z; c.w += xv.w;
                srow[t * 16 + li] = c;
            }
        }
    }
    __syncthreads();

    // Phase B: GEMM. Two groups of 128 threads; group g covers 16 nodes.
    int g  = tid >> 7;
    int t2 = tid & 127;
    int w2 = t2 >> 5, l2 = t2 & 31;
    int jt = l2 & 3;
    int ng = l2 >> 2;
    int fo4 = w2 * 4 + jt;                    // 0..15
    int rowA = g * 16 + ng;
    int rowB = rowA + 8;

    unsigned long long accA0 = 0, accA1 = 0, accB0 = 0, accB1 = 0;
    const float4* W4 = (const float4*)W;      // [512][16]

#pragma unroll 2
    for (int f4 = 0; f4 < 128; f4++) {
        float4 w0 = __ldg(&W4[(f4 * 4 + 0) * 16 + fo4]);
        float4 w1 = __ldg(&W4[(f4 * 4 + 1) * 16 + fo4]);
        float4 w2v = __ldg(&W4[(f4 * 4 + 2) * 16 + fo4]);
        float4 w3 = __ldg(&W4[(f4 * 4 + 3) * 16 + fo4]);
        float4 xa = *(const float4*)&xs[rowA * XSS + f4 * 4];
        float4 xb = *(const float4*)&xs[rowB * XSS + f4 * 4];

        unsigned long long w0lo = pack2(w0.x, w0.y), w0hi = pack2(w0.z, w0.w);
        unsigned long long w1lo = pack2(w1.x, w1.y), w1hi = pack2(w1.z, w1.w);
        unsigned long long w2lo = pack2(w2v.x, w2v.y), w2hi = pack2(w2v.z, w2v.w);
        unsigned long long w3lo = pack2(w3.x, w3.y), w3hi = pack2(w3.z, w3.w);

        unsigned long long xa0 = pack2(xa.x, xa.x), xa1 = pack2(xa.y, xa.y);
        unsigned long long xa2 = pack2(xa.z, xa.z), xa3 = pack2(xa.w, xa.w);
        FMA2(accA0, xa0, w0lo); FMA2(accA1, xa0, w0hi);
        FMA2(accA0, xa1, w1lo); FMA2(accA1, xa1, w1hi);
        FMA2(accA0, xa2, w2lo); FMA2(accA1, xa2, w2hi);
        FMA2(accA0, xa3, w3lo); FMA2(accA1, xa3, w3hi);

        unsigned long long xb0 = pack2(xb.x, xb.x), xb1 = pack2(xb.y, xb.y);
        unsigned long long xb2 = pack2(xb.z, xb.z), xb3 = pack2(xb.w, xb.w);
        FMA2(accB0, xb0, w0lo); FMA2(accB1, xb0, w0hi);
        FMA2(accB0, xb1, w1lo); FMA2(accB1, xb1, w1hi);
        FMA2(accB0, xb2, w2lo); FMA2(accB1, xb2, w2hi);
        FMA2(accB0, xb3, w3lo); FMA2(accB1, xb3, w3hi);
    }

    float4 bv = __ldg(&((const float4*)bias)[fo4]);
    float2 a0 = unpack2(accA0), a1 = unpack2(accA1);
    float2 b0 = unpack2(accB0), b1 = unpack2(accB1);
    float4 ra, rb;
    ra.x = fmaxf(a0.x + bv.x, 0.f); ra.y = fmaxf(a0.y + bv.y, 0.f);
    ra.z = fmaxf(a1.x + bv.z, 0.f); ra.w = fmaxf(a1.y + bv.w, 0.f);
    rb.x = fmaxf(b0.x + bv.x, 0.f); rb.y = fmaxf(b0.y + bv.y, 0.f);
    rb.z = fmaxf(b1.x + bv.z, 0.f); rb.w = fmaxf(b1.y + bv.w, 0.f);
    ((float4*)out)[(size_t)(nb + rowA) * 16 + fo4] = ra;
    ((float4*)out)[(size_t)(nb + rowB) * 16 + fo4] = rb;
}

// ---------------- ssl = h2 @ Wssl + bssl ----------------
__global__ void __launch_bounds__(256) k_ssl(const float* __restrict__ h2,
                                             const float* __restrict__ Wssl,
                                             const float* __restrict__ bssl,
                                             float* __restrict__ out) {
    __shared__ float ws[64 * 64];
    __shared__ float hs[4 * 64];
    int tid = threadIdx.x;
    int nb  = blockIdx.x * 4;

    {
        float4* wsv = (float4*)ws;
        const float4* Wv = (const float4*)Wssl;
#pragma unroll
        for (int k = 0; k < 4; k++) wsv[tid + k * 256] = Wv[tid + k * 256];
        hs[tid] = h2[(size_t)nb * 64 + tid];
    }
    __syncthreads();

    int nl = tid >> 6;
    int fo = tid & 63;
    float a = __ldg(&bssl[fo]);
#pragma unroll 8
    for (int fin = 0; fin < 64; ++fin)
        a += hs[nl * 64 + fin] * ws[fin * 64 + fo];
    out[(size_t)(nb + nl) * 64 + fo] = a;
}

// ---------------- launch ----------------
extern "C" void kernel_launch(void* const* d_in, const int* in_sizes, int n_in,
                              void* d_out, int out_size) {
    const float* x    = (const float*)d_in[0];
    const void*  ei   = d_in[1];
    const void*  ti   = d_in[2];
    const float* W1   = (const float*)d_in[3];
    const float* b1   = (const float*)d_in[4];
    const float* W2   = (const float*)d_in[5];
    const float* b2   = (const float*)d_in[6];
    const float* Wssl = (const float*)d_in[7];
    const float* bssl = (const float*)d_in[8];
    float* out_h   = (float*)d_out;
    float* out_ssl = (float*)d_out + (size_t)NN * 64;

    float* dh1;  cudaGetSymbolAddress((void**)&dh1, g_h1);

    static int smem_set = 0;
    if (!smem_set) {
        cudaFuncSetAttribute(k_fused, cudaFuncAttributeMaxDynamicSharedMemorySize,
                             FUSED_SMEM);
        smem_set = 1;
    }

    // counting sort of edges by dst
    k_detect<<<1, 256>>>((const int*)ei);
    k_zero_cnt<<<(NN + 255) / 256, 256>>>();
    k_prep_hist<<<EE / 256, 256>>>(ei, ti);
    k_scan<<<1, 1024>>>();
    k_permute<<<EE / 256, 256>>>();

    // layer 1 (fused aggregate + GEMM + bias + relu)
    k_fused<<<NN / DPB, 256, FUSED_SMEM>>>(x, W1, b1, dh1);
    // layer 2
    k_fused<<<NN / DPB, 256, FUSED_SMEM>>>(dh1, W2, b2, out_h);

    // ssl head
    k_ssl<<<NN / 4, 256>>>(out_h, Wssl, bssl, out_ssl);
}

// round 5
// speedup vs baseline: 1.4088x; 1.4088x over previous
#include <cuda_runtime.h>
#include <stdint.h>

#define NN 100000
#define EE 3200000
#define TT 8
#define FF 64

// ---------------- device scratch (allocation-free) ----------------
__device__ float g_y[(size_t)TT * NN * FF];   // 204.8 MB: y[t*N+n][f]
__device__ float g_hacc[(size_t)NN * FF];     // 25.6 MB, zero-init, kept zeroed
__device__ float g_h1[(size_t)NN * FF];       // 25.6 MB
__device__ float g_V1[64 * 512];              // permuted W1: V[fin][t*64+fout]
__device__ float g_V2[64 * 512];
__device__ int2  g_edge[EE];                  // {t*N+src, dst}, partitioned by t
__device__ int   g_tcnt[TT];
__device__ int   g_tcur[TT];
__device__ int   g_mode;                      // 1 = indices are int64, 0 = int32

// ---------------- dtype detection ----------------
__global__ void k_detect(const int* __restrict__ ei) {
    __shared__ int any_nonzero;
    if (threadIdx.x == 0) any_nonzero = 0;
    __syncthreads();
    int v = ei[2 * threadIdx.x + 1];
    if (v != 0) atomicExch(&any_nonzero, 1);
    __syncthreads();
    if (threadIdx.x == 0) g_mode = (any_nonzero == 0) ? 1 : 0;
}

__global__ void k_zero_t(void) {
    if (threadIdx.x < TT) g_tcnt[threadIdx.x] = 0;
}

// ---------------- t histogram (block-aggregated) ----------------
__global__ void k_hist_t(const void* __restrict__ ti_raw) {
    __shared__ int scnt[TT];
    int tid = threadIdx.x;
    if (tid < TT) scnt[tid] = 0;
    __syncthreads();
    int e = blockIdx.x * 256 + tid;
    int t;
    if (g_mode) t = (int)((const long long*)ti_raw)[e];
    else        t = ((const int*)ti_raw)[e];
    atomicAdd(&scnt[t], 1);
    __syncthreads();
    if (tid < TT) atomicAdd(&g_tcnt[tid], scnt[tid]);
}

// ---------------- tiny scan of 8 counters ----------------
__global__ void k_scan_t(void) {
    if (threadIdx.x == 0) {
        int run = 0;
        for (int t = 0; t < TT; t++) {
            g_tcur[t] = run;
            run += g_tcnt[t];
        }
    }
}

// ---------------- partition edges by t ----------------
__global__ void k_partition(const void* __restrict__ ei_raw,
                            const void* __restrict__ ti_raw) {
    __shared__ int scnt[TT];
    __shared__ int sbase[TT];
    int tid = threadIdx.x;
    if (tid < TT) scnt[tid] = 0;
    __syncthreads();

    int e = blockIdx.x * 256 + tid;
    int src, dst, t;
    if (g_mode) {
        const long long* ei = (const long long*)ei_raw;
        const long long* ti = (const long long*)ti_raw;
        src = (int)ei[e];
        dst = (int)ei[(size_t)EE + e];
        t   = (int)ti[e];
    } else {
        const int* ei = (const int*)ei_raw;
        const int* ti = (const int*)ti_raw;
        src = ei[e];
        dst = ei[EE + e];
        t   = ti[e];
    }
    int pos = atomicAdd(&scnt[t], 1);
    __syncthreads();
    if (tid < TT) sbase[tid] = atomicAdd(&g_tcur[tid], scnt[tid]);
    __syncthreads();
    g_edge[sbase[t] + pos] = make_int2(t * NN + src, dst);
}

// ---------------- weight permute: V[fin*512 + t*64+fo] ----------------
__global__ void k_prep_w(const float* __restrict__ W, float* __restrict__ V) {
    int idx = blockIdx.x * blockDim.x + threadIdx.x;   // < 32768
    int fin = idx >> 9;
    int j   = idx & 511;
    int t   = j >> 6;
    int fo  = j & 63;
    V[idx] = W[((t << 6) + fin) * 64 + fo];
}

// ---------------- y[t*N+n][:] = in[n][:] @ W_t  (f32x2 packed FMA) ----------
#define FMA2(acc, a, b) asm("fma.rn.f32x2 %0, %1, %2, %0;" : "+l"(acc) : "l"(a), "l"(b))
__global__ void __launch_bounds__(128) k_gemm(const float* __restrict__ in,
                                              const float* __restrict__ V,
                                              float* __restrict__ y) {
    __shared__ float xs[16][64];
    int tid = threadIdx.x;
    int nb  = blockIdx.x * 16;

    {
        const float4* inv = (const float4*)(in + (size_t)nb * 64);
        float4* xsv = (float4*)&xs[0][0];
        xsv[tid]       = inv[tid];
        xsv[tid + 128] = inv[tid + 128];
    }
    __syncthreads();

    int jt = tid & 31;
    int ng = tid >> 5;

    unsigned long long acc[4][4][2];
#pragma unroll
    for (int i = 0; i < 4; i++)
#pragma unroll
        for (int s = 0; s < 4; s++) { acc[i][s][0] = 0ull; acc[i][s][1] = 0ull; }

    const ulonglong2* Vr = (const ulonglong2*)V;

#pragma unroll 4
    for (int fin = 0; fin < 64; ++fin) {
        unsigned long long xv[4];
#pragma unroll
        for (int i = 0; i < 4; i++) {
            unsigned int xb = __float_as_uint(xs[(ng << 2) + i][fin]);
            asm("mov.b64 %0, {%1, %1};" : "=l"(xv[i]) : "r"(xb));
        }
#pragma unroll
        for (int s = 0; s < 4; s++) {
            ulonglong2 w = __ldg(&Vr[fin * 128 + jt + s * 32]);
#pragma unroll
            for (int i = 0; i < 4; i++) {
                FMA2(acc[i][s][0], xv[i], w.x);
                FMA2(acc[i][s][1], xv[i], w.y);
            }
        }
    }

    ulonglong2* yv = (ulonglong2*)y;
#pragma unroll
    for (int s = 0; s < 4; s++) {
        int j4 = jt + s * 32;
        int t  = j4 >> 4;
        int c4 = j4 & 15;
#pragma unroll
        for (int i = 0; i < 4; i++) {
            int node = nb + (ng << 2) + i;
            ulonglong2 o;
            o.x = acc[i][s][0];
            o.y = acc[i][s][1];
            yv[(size_t)(t * NN + node) * 16 + c4] = o;
        }
    }
}

// ---------------- scatter: hacc[dst] += y[t*N+src]  (float4 atomics) --------
// edges are t-partitioned -> gather working set per region is y_t (L2-resident)
__global__ void __launch_bounds__(256) k_scatter(void) {
    size_t idx = (size_t)blockIdx.x * 256 + threadIdx.x;   // < E*16
    int e = (int)(idx >> 4);
    int c = (int)(idx & 15);
    int2 ed = __ldg(&g_edge[e]);
    const float4* yv = (const float4*)g_y;
    float4 v = __ldg(&yv[(size_t)ed.x * 16 + c]);
    float4* hv = (float4*)g_hacc;
    atomicAdd(&hv[(size_t)ed.y * 16 + c], v);
}

// ---------------- epilogue: out = relu(hacc + b); hacc = 0 ----------------
__global__ void __launch_bounds__(256) k_bias_relu_reset(const float* __restrict__ bias,
                                                         float* __restrict__ out) {
    int i = blockIdx.x * 256 + threadIdx.x;   // < N*16
    float4* hv = (float4*)g_hacc;
    float4 v = hv[i];
    hv[i] = make_float4(0.f, 0.f, 0.f, 0.f);
    float4 b = __ldg(&((const float4*)bias)[i & 15]);
    float4 r;
    r.x = fmaxf(v.x + b.x, 0.f);
    r.y = fmaxf(v.y + b.y, 0.f);
    r.z = fmaxf(v.z + b.z, 0.f);
    r.w = fmaxf(v.w + b.w, 0.f);
    ((float4*)out)[i] = r;
}

// ---------------- ssl = h2 @ Wssl + bssl ----------------
__global__ void __launch_bounds__(256) k_ssl(const float* __restrict__ h2,
                                             const float* __restrict__ Wssl,
                                             const float* __restrict__ bssl,
                                             float* __restrict__ out) {
    __shared__ float ws[64 * 64];
    __shared__ float hs[4 * 64];
    int tid = threadIdx.x;
    int nb  = blockIdx.x * 4;

    {
        float4* wsv = (float4*)ws;
        const float4* Wv = (const float4*)Wssl;
#pragma unroll
        for (int k = 0; k < 4; k++) wsv[tid + k * 256] = Wv[tid + k * 256];
        hs[tid] = h2[(size_t)nb * 64 + tid];
    }
    __syncthreads();

    int nl = tid >> 6;
    int fo = tid & 63;
    float a = __ldg(&bssl[fo]);
#pragma unroll 8
    for (int fin = 0; fin < 64; ++fin)
        a += hs[nl * 64 + fin] * ws[fin * 64 + fo];
    out[(size_t)(nb + nl) * 64 + fo] = a;
}

// ---------------- launch ----------------
extern "C" void kernel_launch(void* const* d_in, const int* in_sizes, int n_in,
                              void* d_out, int out_size) {
    const float* x    = (const float*)d_in[0];
    const void*  ei   = d_in[1];
    const void*  ti   = d_in[2];
    const float* W1   = (const float*)d_in[3];
    const float* b1   = (const float*)d_in[4];
    const float* W2   = (const float*)d_in[5];
    const float* b2   = (const float*)d_in[6];
    const float* Wssl = (const float*)d_in[7];
    const float* bssl = (const float*)d_in[8];
    float* out_h   = (float*)d_out;
    float* out_ssl = (float*)d_out + (size_t)NN * 64;

    float* dV1;  cudaGetSymbolAddress((void**)&dV1, g_V1);
    float* dV2;  cudaGetSymbolAddress((void**)&dV2, g_V2);
    float* dy;   cudaGetSymbolAddress((void**)&dy, g_y);
    float* dh1;  cudaGetSymbolAddress((void**)&dh1, g_h1);

    // partition edges by t (8 buckets)
    k_detect<<<1, 256>>>((const int*)ei);
    k_zero_t<<<1, 32>>>();
    k_hist_t<<<EE / 256, 256>>>(ti);
    k_scan_t<<<1, 32>>>();
    k_partition<<<EE / 256, 256>>>(ei, ti);

    k_prep_w<<<32768 / 256, 256>>>(W1, dV1);
    k_prep_w<<<32768 / 256, 256>>>(W2, dV2);

    // layer 1
    k_gemm<<<NN / 16, 128>>>(x, dV1, dy);
    k_scatter<<<(EE * 16) / 256, 256>>>();
    k_bias_relu_reset<<<(NN * 16) / 256, 256>>>(b1, dh1);

    // layer 2
    k_gemm<<<NN / 16, 128>>>(dh1, dV2, dy);
    k_scatter<<<(EE * 16) / 256, 256>>>();
    k_bias_relu_reset<<<(NN * 16) / 256, 256>>>(b2, out_h);

    // ssl head
    k_ssl<<<NN / 4, 256>>>(out_h, Wssl, bssl, out_ssl);
}